// round 1
// baseline (speedup 1.0000x reference)
#include <cuda_runtime.h>
#include <cuda_bf16.h>
#include <mma.h>
#include <math.h>

using namespace nvcuda;

#define B_   4
#define L_   2048
#define D_   2048
#define H_   16
#define HD_  128
#define BL_  (B_*L_)          // 8192
#define SM_SCALE 0.08838834764831845f   // 1/sqrt(128)

// ---------------- scratch (device globals; no allocation allowed) ----------------
__device__ float g_Q[BL_*D_];   // [b,h,l,d] after proj(+norm+rope+scale)
__device__ float g_K[BL_*D_];   // [b,h,l,d]
__device__ float g_V[BL_*D_];   // [b,h,l,d]
__device__ float g_A[BL_*D_];   // attention out, [b,l,h,d] = [8192,2048]

// ================================================================================
// TF32 GEMM:  C[m,n] = sum_k A[m,k] * W[n,k]   (A:[M,K] row-major, W:[N,K] row-major)
// mode 0: C row-major [M, 2048]
// mode 1: write tile to [b,h,l,d] layout (head-transposed), BN=128 == one head
// ================================================================================
#define GBM 128
#define GBN 128
#define GBK 32
#define GLD 40   // BK + 8 pad

__global__ __launch_bounds__(256) void gemm_tf32_kernel(
    const float* __restrict__ A, const float* __restrict__ W,
    float* __restrict__ C, int K, int mode)
{
    __shared__ float As[GBM*GLD];
    __shared__ float Bs[GBN*GLD];

    const int tid  = threadIdx.x;
    const int warp = tid >> 5;
    const int wm   = warp >> 2;     // 0..1
    const int wn   = warp & 3;      // 0..3
    const int rowBase = blockIdx.y * GBM;
    const int colBase = blockIdx.x * GBN;

    wmma::fragment<wmma::accumulator,16,16,8,float> cf[4][2];
    #pragma unroll
    for (int i=0;i<4;i++)
        #pragma unroll
        for (int j=0;j<2;j++)
            wmma::fill_fragment(cf[i][j], 0.0f);

    for (int k0 = 0; k0 < K; k0 += GBK) {
        // load A & W tiles (128x32 each), convert to tf32 in smem
        #pragma unroll
        for (int p=0;p<4;p++){
            int idx = tid + p*256;      // 0..1023 float4 slots
            int r   = idx >> 3;         // row 0..127
            int c4  = idx & 7;          // float4 col 0..7
            float4 va = *(const float4*)(A + (size_t)(rowBase+r)*K + k0 + c4*4);
            float* da = As + r*GLD + c4*4;
            da[0]=wmma::__float_to_tf32(va.x); da[1]=wmma::__float_to_tf32(va.y);
            da[2]=wmma::__float_to_tf32(va.z); da[3]=wmma::__float_to_tf32(va.w);
            float4 vb = *(const float4*)(W + (size_t)(colBase+r)*K + k0 + c4*4);
            float* db = Bs + r*GLD + c4*4;
            db[0]=wmma::__float_to_tf32(vb.x); db[1]=wmma::__float_to_tf32(vb.y);
            db[2]=wmma::__float_to_tf32(vb.z); db[3]=wmma::__float_to_tf32(vb.w);
        }
        __syncthreads();

        #pragma unroll
        for (int kk=0; kk<4; kk++) {
            wmma::fragment<wmma::matrix_a,16,16,8,wmma::precision::tf32,wmma::row_major> af[4];
            #pragma unroll
            for (int i=0;i<4;i++)
                wmma::load_matrix_sync(af[i], As + (wm*64 + i*16)*GLD + kk*8, GLD);
            wmma::fragment<wmma::matrix_b,16,16,8,wmma::precision::tf32,wmma::col_major> bf[2];
            #pragma unroll
            for (int j=0;j<2;j++)
                wmma::load_matrix_sync(bf[j], Bs + (wn*32 + j*16)*GLD + kk*8, GLD);
            #pragma unroll
            for (int i=0;i<4;i++)
                #pragma unroll
                for (int j=0;j<2;j++)
                    wmma::mma_sync(cf[i][j], af[i], bf[j], cf[i][j]);
        }
        __syncthreads();
    }

    if (mode == 0) {
        #pragma unroll
        for (int i=0;i<4;i++){
            int m = rowBase + wm*64 + i*16;
            #pragma unroll
            for (int j=0;j<2;j++){
                int n = colBase + wn*32 + j*16;
                wmma::store_matrix_sync(C + (size_t)m*D_ + n, cf[i][j], D_, wmma::mem_row_major);
            }
        }
    } else {
        // head-transposed: out[((b*H + h)*L + l)*HD + d], h = blockIdx.x
        const int hh = blockIdx.x;
        #pragma unroll
        for (int i=0;i<4;i++){
            int m = rowBase + wm*64 + i*16;
            int b = m >> 11;            // L_ = 2048
            int l = m & 2047;
            float* dst = C + (((size_t)b*H_ + hh)*L_ + l)*HD_ + wn*32;
            #pragma unroll
            for (int j=0;j<2;j++)
                wmma::store_matrix_sync(dst + j*16, cf[i][j], HD_, wmma::mem_row_major);
        }
    }
}

// ================================================================================
// In-place per-head RMSNorm + RoPE on g_Q / g_K ([b,h,l,d]); Q also gets SM_SCALE.
// One warp per (b,h,l) head vector; lane owns 4 consecutive d (float4).
// ================================================================================
__global__ __launch_bounds__(256) void normrope_kernel(
    float* __restrict__ Q, float* __restrict__ Kx,
    const float* __restrict__ cosq, const float* __restrict__ sinq,
    const float* __restrict__ cosk, const float* __restrict__ sink,
    const float* __restrict__ qg,   const float* __restrict__ kg)
{
    const unsigned FULL = 0xffffffffu;
    int gw   = (blockIdx.x*256 + threadIdx.x) >> 5;   // 0 .. B*H*L-1 (== (b,h,l) in order)
    int lane = threadIdx.x & 31;
    int l    = gw % L_;
    int b    = gw / (H_*L_);
    int d0   = lane*4;
    size_t base  = (size_t)gw * HD_;
    size_t cbase = ((size_t)b*L_ + l)*HD_ + d0;
    float sgn = (lane < 16) ? -1.0f : 1.0f;

    // ---- Q ----
    {
        float4 v = *(const float4*)(Q + base + d0);
        float ss = v.x*v.x + v.y*v.y + v.z*v.z + v.w*v.w;
        #pragma unroll
        for (int o=16;o;o>>=1) ss += __shfl_xor_sync(FULL, ss, o);
        float rs = rsqrtf(ss*(1.0f/128.0f) + 1e-6f);
        float4 g = *(const float4*)(qg + d0);
        float4 n; n.x=v.x*rs*g.x; n.y=v.y*rs*g.y; n.z=v.z*rs*g.z; n.w=v.w*rs*g.w;
        float4 p;
        p.x=__shfl_xor_sync(FULL,n.x,16); p.y=__shfl_xor_sync(FULL,n.y,16);
        p.z=__shfl_xor_sync(FULL,n.z,16); p.w=__shfl_xor_sync(FULL,n.w,16);
        float4 c = *(const float4*)(cosq + cbase);
        float4 s = *(const float4*)(sinq + cbase);
        float4 o4;
        o4.x = (n.x*c.x + sgn*p.x*s.x) * SM_SCALE;
        o4.y = (n.y*c.y + sgn*p.y*s.y) * SM_SCALE;
        o4.z = (n.z*c.z + sgn*p.z*s.z) * SM_SCALE;
        o4.w = (n.w*c.w + sgn*p.w*s.w) * SM_SCALE;
        *(float4*)(Q + base + d0) = o4;
    }
    // ---- K ----
    {
        float4 v = *(const float4*)(Kx + base + d0);
        float ss = v.x*v.x + v.y*v.y + v.z*v.z + v.w*v.w;
        #pragma unroll
        for (int o=16;o;o>>=1) ss += __shfl_xor_sync(FULL, ss, o);
        float rs = rsqrtf(ss*(1.0f/128.0f) + 1e-6f);
        float4 g = *(const float4*)(kg + d0);
        float4 n; n.x=v.x*rs*g.x; n.y=v.y*rs*g.y; n.z=v.z*rs*g.z; n.w=v.w*rs*g.w;
        float4 p;
        p.x=__shfl_xor_sync(FULL,n.x,16); p.y=__shfl_xor_sync(FULL,n.y,16);
        p.z=__shfl_xor_sync(FULL,n.z,16); p.w=__shfl_xor_sync(FULL,n.w,16);
        float4 c = *(const float4*)(cosk + cbase);
        float4 s = *(const float4*)(sink + cbase);
        float4 o4;
        o4.x = n.x*c.x + sgn*p.x*s.x;
        o4.y = n.y*c.y + sgn*p.y*s.y;
        o4.z = n.z*c.z + sgn*p.z*s.z;
        o4.w = n.w*c.w + sgn*p.w*s.w;
        *(float4*)(Kx + base + d0) = o4;
    }
}

// ================================================================================
// Flash attention (non-causal), tf32 wmma, online softmax through smem.
// CTA: 256 threads (8 warps), BQ=64 q-rows, BKT=64 k-cols per iter, hd=128.
// grid = (L/64, B*H)
// ================================================================================
#define QLD 136   // 128 + 8
#define SLD 72    // 64 + 8
#define OLDM 132  // 128 + 4
#define FL_SMEM_FLOATS (3*64*QLD + 64*SLD + 2*64*OLDM + 3*64 + 64*4)
#define FL_SMEM_BYTES  (FL_SMEM_FLOATS*4)   // 192256

__global__ __launch_bounds__(256) void flash_kernel(
    const float* __restrict__ Q, const float* __restrict__ Kt,
    const float* __restrict__ Vt, float* __restrict__ Out)
{
    extern __shared__ float sm[];
    float* Qs   = sm;                  // 64 x QLD
    float* Ks   = Qs  + 64*QLD;        // 64 x QLD
    float* Vs   = Ks  + 64*QLD;        // 64 x QLD
    float* Ss   = Vs  + 64*QLD;        // 64 x SLD  (scores, then P in tf32)
    float* Os   = Ss  + 64*SLD;        // 64 x OLDM (running O, fp32)
    float* Ot   = Os  + 64*OLDM;       // 64 x OLDM (fresh P*V)
    float* mrow = Ot  + 64*OLDM;       // 64
    float* lrow = mrow + 64;           // 64
    float* arow = lrow + 64;           // 64
    float* psum = arow + 64;           // 64 x 4

    const int tid = threadIdx.x;
    const int w   = tid >> 5;
    const int wr  = w >> 1;            // 0..3  (16-row slice)
    const int wc  = w & 1;             // 0..1
    const int bh  = blockIdx.y;
    const int qt  = blockIdx.x;
    const int b   = bh >> 4;
    const int h   = bh & 15;

    const float* Qg = Q  + ((size_t)bh*L_ + qt*64)*HD_;
    const float* Kg = Kt + (size_t)bh*L_*HD_;
    const float* Vg = Vt + (size_t)bh*L_*HD_;

    // load Q tile (already scaled), tf32-convert
    #pragma unroll
    for (int p=0;p<8;p++){
        int idx = tid + p*256;
        int r = idx >> 5, c4 = idx & 31;
        float4 v = *(const float4*)(Qg + r*HD_ + c4*4);
        float* d = Qs + r*QLD + c4*4;
        d[0]=wmma::__float_to_tf32(v.x); d[1]=wmma::__float_to_tf32(v.y);
        d[2]=wmma::__float_to_tf32(v.z); d[3]=wmma::__float_to_tf32(v.w);
    }
    if (tid < 64) { mrow[tid] = -1e30f; lrow[tid] = 0.0f; }
    #pragma unroll
    for (int p=0;p<33;p++){ int idx = tid + p*256; Os[idx] = 0.0f; }   // 33*256 == 64*OLDM
    __syncthreads();

    for (int kt=0; kt<L_/64; kt++) {
        // load K & V tiles, tf32-convert
        const float* Kgt = Kg + (size_t)kt*64*HD_;
        const float* Vgt = Vg + (size_t)kt*64*HD_;
        #pragma unroll
        for (int p=0;p<8;p++){
            int idx = tid + p*256;
            int r = idx >> 5, c4 = idx & 31;
            float4 vk = *(const float4*)(Kgt + r*HD_ + c4*4);
            float* dk = Ks + r*QLD + c4*4;
            dk[0]=wmma::__float_to_tf32(vk.x); dk[1]=wmma::__float_to_tf32(vk.y);
            dk[2]=wmma::__float_to_tf32(vk.z); dk[3]=wmma::__float_to_tf32(vk.w);
            float4 vv = *(const float4*)(Vgt + r*HD_ + c4*4);
            float* dv = Vs + r*QLD + c4*4;
            dv[0]=wmma::__float_to_tf32(vv.x); dv[1]=wmma::__float_to_tf32(vv.y);
            dv[2]=wmma::__float_to_tf32(vv.z); dv[3]=wmma::__float_to_tf32(vv.w);
        }
        __syncthreads();

        // S = Q * K^T  (each warp: 16 rows x 32 cols)
        {
            wmma::fragment<wmma::accumulator,16,16,8,float> sc[2];
            wmma::fill_fragment(sc[0],0.0f); wmma::fill_fragment(sc[1],0.0f);
            #pragma unroll
            for (int ks=0; ks<16; ks++){
                wmma::fragment<wmma::matrix_a,16,16,8,wmma::precision::tf32,wmma::row_major> af;
                wmma::load_matrix_sync(af, Qs + (wr*16)*QLD + ks*8, QLD);
                #pragma unroll
                for (int j=0;j<2;j++){
                    wmma::fragment<wmma::matrix_b,16,16,8,wmma::precision::tf32,wmma::col_major> bf;
                    wmma::load_matrix_sync(bf, Ks + (wc*32 + j*16)*QLD + ks*8, QLD);
                    wmma::mma_sync(sc[j], af, bf, sc[j]);
                }
            }
            wmma::store_matrix_sync(Ss + (wr*16)*SLD + wc*32,      sc[0], SLD, wmma::mem_row_major);
            wmma::store_matrix_sync(Ss + (wr*16)*SLD + wc*32 + 16, sc[1], SLD, wmma::mem_row_major);
        }
        __syncthreads();

        // phase a: row max + alpha (one thread per row)
        if (tid < 64) {
            int r = tid;
            float mold = mrow[r];
            float mx = mold;
            const float* srow = Ss + r*SLD;
            #pragma unroll
            for (int c=0;c<64;c++) mx = fmaxf(mx, srow[c]);
            float al = __expf(mold - mx);
            mrow[r] = mx; arow[r] = al; lrow[r] *= al;
        }
        __syncthreads();

        // phase c: exp -> P (tf32), partial row sums; rescale Os by alpha
        {
            int r = tid >> 2, q = tid & 3;
            float mx = mrow[r];
            float s = 0.0f;
            float* srow = Ss + r*SLD + q*16;
            #pragma unroll
            for (int jj=0;jj<16;jj++){
                float pv = __expf(srow[jj] - mx);
                s += pv;
                srow[jj] = wmma::__float_to_tf32(pv);
            }
            psum[r*4 + q] = s;
            #pragma unroll
            for (int p2=0;p2<32;p2++){
                int idx = tid + p2*256;
                int ro = idx >> 7, co = idx & 127;
                Os[ro*OLDM + co] *= arow[ro];
            }
        }
        __syncthreads();

        // PV: each warp 16 rows x 64 cols
        {
            wmma::fragment<wmma::accumulator,16,16,8,float> oc[4];
            #pragma unroll
            for (int j=0;j<4;j++) wmma::fill_fragment(oc[j], 0.0f);
            #pragma unroll
            for (int ks=0; ks<8; ks++){
                wmma::fragment<wmma::matrix_a,16,16,8,wmma::precision::tf32,wmma::row_major> pf;
                wmma::load_matrix_sync(pf, Ss + (wr*16)*SLD + ks*8, SLD);
                #pragma unroll
                for (int j=0;j<4;j++){
                    wmma::fragment<wmma::matrix_b,16,16,8,wmma::precision::tf32,wmma::row_major> vf;
                    wmma::load_matrix_sync(vf, Vs + (ks*8)*QLD + wc*64 + j*16, QLD);
                    wmma::mma_sync(oc[j], pf, vf, oc[j]);
                }
            }
            #pragma unroll
            for (int j=0;j<4;j++)
                wmma::store_matrix_sync(Ot + (wr*16)*OLDM + wc*64 + j*16, oc[j], OLDM, wmma::mem_row_major);
        }
        __syncthreads();

        // merge: Os += Ot ; lrow += partial sums
        #pragma unroll
        for (int p2=0;p2<32;p2++){
            int idx = tid + p2*256;
            int ro = idx >> 7, co = idx & 127;
            Os[ro*OLDM + co] += Ot[ro*OLDM + co];
        }
        if (tid < 64)
            lrow[tid] += psum[tid*4] + psum[tid*4+1] + psum[tid*4+2] + psum[tid*4+3];
        __syncthreads();
    }

    // epilogue: normalize and write to [b,l,h,d]
    #pragma unroll
    for (int p2=0;p2<32;p2++){
        int idx = tid + p2*256;
        int r = idx >> 7, c = idx & 127;
        float o = Os[r*OLDM + c] / lrow[r];
        Out[ (((size_t)b*L_ + qt*64 + r)*H_ + h)*HD_ + c ] = o;
    }
}

// ================================================================================
extern "C" void kernel_launch(void* const* d_in, const int* in_sizes, int n_in,
                              void* d_out, int out_size)
{
    const float* x    = (const float*)d_in[0];
    const float* cosq = (const float*)d_in[1];
    const float* sinq = (const float*)d_in[2];
    const float* cosk = (const float*)d_in[3];
    const float* sink = (const float*)d_in[4];
    const float* Wq   = (const float*)d_in[5];
    const float* Wk   = (const float*)d_in[6];
    const float* Wv   = (const float*)d_in[7];
    const float* Wo   = (const float*)d_in[8];
    const float* qg   = (const float*)d_in[9];
    const float* kg   = (const float*)d_in[10];
    float* out = (float*)d_out;

    float *Qb, *Kb, *Vb, *Ab;
    cudaGetSymbolAddress((void**)&Qb, g_Q);
    cudaGetSymbolAddress((void**)&Kb, g_K);
    cudaGetSymbolAddress((void**)&Vb, g_V);
    cudaGetSymbolAddress((void**)&Ab, g_A);

    cudaFuncSetAttribute(flash_kernel, cudaFuncAttributeMaxDynamicSharedMemorySize,
                         FL_SMEM_BYTES);

    dim3 gg(D_/GBN, BL_/GBM);   // (16, 64)

    // QKV projections, writing directly head-transposed [b,h,l,d]
    gemm_tf32_kernel<<<gg, 256>>>(x, Wq, Qb, D_, 1);
    gemm_tf32_kernel<<<gg, 256>>>(x, Wk, Kb, D_, 1);
    gemm_tf32_kernel<<<gg, 256>>>(x, Wv, Vb, D_, 1);

    // in-place RMSNorm + RoPE (+ softmax scale folded into Q)
    normrope_kernel<<<(B_*H_*L_)/8, 256>>>(Qb, Kb, cosq, sinq, cosk, sink, qg, kg);

    // flash attention -> g_A in [b,l,h,d]
    flash_kernel<<<dim3(L_/64, B_*H_), 256, FL_SMEM_BYTES>>>(Qb, Kb, Vb, Ab);

    // output projection -> d_out
    gemm_tf32_kernel<<<gg, 256>>>(Ab, Wo, out, D_, 0);
}